// round 5
// baseline (speedup 1.0000x reference)
#include <cuda_runtime.h>
#include <cuda_bf16.h>
#include <stdint.h>
#include <math.h>

#define NTOK 2048
#define EDIM 1024
#define NLAYER 4

// ---------------------------------------------------------------------------
// Scratch (device globals — allocation is forbidden)
// ---------------------------------------------------------------------------
__device__ __nv_bfloat16 g_xhi[NTOK * EDIM], g_xlo[NTOK * EDIM];
__device__ __nv_bfloat16 g_qkvhi[NTOK * 3 * EDIM], g_qkvlo[NTOK * 3 * EDIM];
__device__ float         g_w[NTOK * NTOK];
__device__ __nv_bfloat16 g_whi[NTOK * NTOK], g_wlo[NTOK * NTOK];
__device__ __nv_bfloat16 g_vThi[EDIM * NTOK], g_vTlo[EDIM * NTOK];
__device__ __nv_bfloat16 g_wvhi[NTOK * EDIM], g_wvlo[NTOK * EDIM];
__device__ __nv_bfloat16 g_Wqkvhi[NLAYER * 3 * EDIM * EDIM], g_Wqkvlo[NLAYER * 3 * EDIM * EDIM];
__device__ __nv_bfloat16 g_Wohi[NLAYER * EDIM * EDIM], g_Wolo[NLAYER * EDIM * EDIM];

// ---------------------------------------------------------------------------
// Helpers
// ---------------------------------------------------------------------------
__device__ __forceinline__ uint32_t s2u(const void* p) {
    uint32_t a;
    asm("{ .reg .u64 t; cvta.to.shared.u64 t, %1; cvt.u32.u64 %0, t; }" : "=r"(a) : "l"(p));
    return a;
}
#define CPA(sm, gp) \
    asm volatile("cp.async.cg.shared.global [%0], [%1], 16;" :: "r"(sm), "l"(gp))
#define CPA_COMMIT() asm volatile("cp.async.commit_group;")
#define CPA_WAIT1()  asm volatile("cp.async.wait_group 1;")
#define CPA_WAIT0()  asm volatile("cp.async.wait_group 0;")

#define LDSM4(r0, r1, r2, r3, addr)                                          \
    asm volatile("ldmatrix.sync.aligned.m8n8.x4.shared.b16 {%0,%1,%2,%3}, [%4];" \
                 : "=r"(r0), "=r"(r1), "=r"(r2), "=r"(r3) : "r"(addr))

__device__ __forceinline__ void mma16816(float* c, const uint32_t* a, const uint32_t* b) {
    asm volatile(
        "mma.sync.aligned.m16n8k16.row.col.f32.bf16.bf16.f32 "
        "{%0,%1,%2,%3}, {%4,%5,%6,%7}, {%8,%9}, {%0,%1,%2,%3};"
        : "+f"(c[0]), "+f"(c[1]), "+f"(c[2]), "+f"(c[3])
        : "r"(a[0]), "r"(a[1]), "r"(a[2]), "r"(a[3]), "r"(b[0]), "r"(b[1]));
}

__device__ __forceinline__ uint32_t pack2bf(float a, float b) {
    __nv_bfloat162 t = __floats2bfloat162_rn(a, b);
    return *reinterpret_cast<uint32_t*>(&t);
}

// SMEM geometry: per chunk, 4 tiles of 128 rows x 32 bf16, padded to 80 B/row
// (80B pitch => conflict-free ldmatrix). Tile = 10240 B. Buffer = 4 tiles.
#define TILE_B   10240
#define BUF_B    40960
#define SMEM_BYTES (2 * BUF_B)   // 81920

// ---------------------------------------------------------------------------
// Tensor-core NT GEMM with fused 3-pass bf16 hi/lo split:
//   C[by*128.., bx*128..] = sum_k Ahi*Bhi + Ahi*Blo + Alo*Bhi
//   EPI 0: C fp32 = alpha * acc              (scores)
//   EPI 1: C bf16 hi/lo = acc                (wv)
//   EPI 2: C bf16 hi/lo = acc + bias[col]    (qkv / out-proj)
//   CSKIP: skip blocks strictly above diagonal;  KLIM: Keff = (by+1)*128
//
// Inner loop is PASS-MAJOR per mf: all 4 nf of hi*hi, then hi*lo, then lo*hi.
// Same-accumulator reuse distance = 4 mmas > HMMA latency (was 1 in R4 -> 45%
// tensor pipe from RAW stalls).
// ---------------------------------------------------------------------------
template<int EPI, bool CSKIP, bool KLIM>
__global__ void __launch_bounds__(256, 2) gemm_mma(
    const __nv_bfloat16* __restrict__ Ahi, const __nv_bfloat16* __restrict__ Alo, int lda,
    const __nv_bfloat16* __restrict__ Bhi, const __nv_bfloat16* __restrict__ Blo, int ldb,
    float* __restrict__ Cf,
    __nv_bfloat16* __restrict__ Chi, __nv_bfloat16* __restrict__ Clo, int ldc,
    const float* __restrict__ bias, int K, float alpha)
{
    const int bx = blockIdx.x, by = blockIdx.y;
    if (CSKIP && bx > by) return;
    const int Keff = KLIM ? min(K, (by + 1) * 128) : K;
    const int nch  = Keff / 32;

    extern __shared__ __align__(128) char smem[];
    const uint32_t sb = s2u(smem);

    const int tid  = threadIdx.x;
    const int wid  = tid >> 5, lane = tid & 31;
    const int wm   = (wid & 1) * 64;     // warp m offset (2 warps)
    const int wn   = (wid >> 1) * 32;    // warp n offset (4 warps)

    // Block-level gmem bases
    const __nv_bfloat16* Abh = Ahi + (size_t)(by * 128) * lda;
    const __nv_bfloat16* Abl = Alo + (size_t)(by * 128) * lda;
    const __nv_bfloat16* Bbh = Bhi + (size_t)(bx * 128) * ldb;
    const __nv_bfloat16* Bbl = Blo + (size_t)(bx * 128) * ldb;

    // ldmatrix per-lane address components
    const uint32_t a_row = lane & 15;
    const uint32_t a_k   = (lane >> 4) * 16;
    const uint32_t b_row = (lane & 7) + (lane >> 4) * 8;
    const uint32_t b_k   = ((lane >> 3) & 1) * 16;

    float acc[4][4][4];
#pragma unroll
    for (int i = 0; i < 4; i++)
#pragma unroll
        for (int j = 0; j < 4; j++)
#pragma unroll
            for (int r = 0; r < 4; r++) acc[i][j][r] = 0.f;

    // ---- chunk loader (cp.async, 4 tiles) ----
    auto load_chunk = [&](uint32_t sbuf, int kt) {
#pragma unroll
        for (int i = 0; i < 2; i++) {
            int v = tid * 2 + i;
            int row = v >> 2, c = v & 3;
            uint32_t so = (uint32_t)row * 80 + c * 16;
            size_t ga = (size_t)row * lda + kt + c * 8;
            size_t gb = (size_t)row * ldb + kt + c * 8;
            CPA(sb + sbuf + so,              Abh + ga);
            CPA(sb + sbuf + TILE_B + so,     Abl + ga);
            CPA(sb + sbuf + 2 * TILE_B + so, Bbh + gb);
            CPA(sb + sbuf + 3 * TILE_B + so, Bbl + gb);
        }
    };

    load_chunk(0, 0);
    CPA_COMMIT();

    for (int c = 0; c < nch; c++) {
        const uint32_t buf = (c & 1) ? BUF_B : 0;
        if (c + 1 < nch) {
            load_chunk(buf ^ BUF_B, (c + 1) * 32);
            CPA_COMMIT();
            CPA_WAIT1();
        } else {
            CPA_WAIT0();
        }
        __syncthreads();

#pragma unroll
        for (int k16 = 0; k16 < 2; k16++) {
            uint32_t bh[8], bl[8];
            {
                uint32_t bb = sb + buf + 2 * TILE_B
                            + (wn + b_row) * 80 + k16 * 32 + b_k;
                LDSM4(bh[0], bh[1], bh[2], bh[3], bb);
                LDSM4(bh[4], bh[5], bh[6], bh[7], bb + 16 * 80);
                LDSM4(bl[0], bl[1], bl[2], bl[3], bb + TILE_B);
                LDSM4(bl[4], bl[5], bl[6], bl[7], bb + TILE_B + 16 * 80);
            }
#pragma unroll
            for (int mf = 0; mf < 4; mf++) {
                uint32_t ah[4], al[4];
                uint32_t ab = sb + buf
                            + (wm + mf * 16 + a_row) * 80 + k16 * 32 + a_k;
                LDSM4(ah[0], ah[1], ah[2], ah[3], ab);
                LDSM4(al[0], al[1], al[2], al[3], ab + TILE_B);
                // pass-major: same-acc reuse distance = 4 mmas
#pragma unroll
                for (int nf = 0; nf < 4; nf++)
                    mma16816(acc[mf][nf], ah, bh + nf * 2);   // hi*hi
#pragma unroll
                for (int nf = 0; nf < 4; nf++)
                    mma16816(acc[mf][nf], ah, bl + nf * 2);   // hi*lo
#pragma unroll
                for (int nf = 0; nf < 4; nf++)
                    mma16816(acc[mf][nf], al, bh + nf * 2);   // lo*hi
            }
        }
        __syncthreads();
    }

    // ---- epilogue ----
#pragma unroll
    for (int mf = 0; mf < 4; mf++) {
#pragma unroll
        for (int nf = 0; nf < 4; nf++) {
            const float* cc = acc[mf][nf];
            int row0 = by * 128 + wm + mf * 16 + (lane >> 2);
            int col  = bx * 128 + wn + nf * 8 + (lane & 3) * 2;
            if (EPI == 0) {
                float2 v0 = make_float2(alpha * cc[0], alpha * cc[1]);
                float2 v1 = make_float2(alpha * cc[2], alpha * cc[3]);
                *(float2*)(Cf + (size_t)row0 * ldc + col) = v0;
                *(float2*)(Cf + (size_t)(row0 + 8) * ldc + col) = v1;
            } else {
                float b0 = 0.f, b1 = 0.f;
                if (EPI == 2) { b0 = bias[col]; b1 = bias[col + 1]; }
                float v0 = cc[0] + b0, v1 = cc[1] + b1;
                float v2 = cc[2] + b0, v3 = cc[3] + b1;
                float h0 = __bfloat162float(__float2bfloat16_rn(v0));
                float h1 = __bfloat162float(__float2bfloat16_rn(v1));
                float h2 = __bfloat162float(__float2bfloat16_rn(v2));
                float h3 = __bfloat162float(__float2bfloat16_rn(v3));
                size_t o0 = (size_t)row0 * ldc + col;
                size_t o1 = (size_t)(row0 + 8) * ldc + col;
                *(uint32_t*)(Chi + o0) = pack2bf(h0, h1);
                *(uint32_t*)(Clo + o0) = pack2bf(v0 - h0, v1 - h1);
                *(uint32_t*)(Chi + o1) = pack2bf(h2, h3);
                *(uint32_t*)(Clo + o1) = pack2bf(v2 - h2, v3 - h3);
            }
        }
    }
}

// ---------------------------------------------------------------------------
// Causal softmax over row i (len = i+1) from fp32 scores; writes bf16 hi/lo
// weights (zero-padded) and accumulates 0.25*w into out.
// ---------------------------------------------------------------------------
__global__ __launch_bounds__(256) void softmax_causal_acc(
    const float* __restrict__ w,
    __nv_bfloat16* __restrict__ whi, __nv_bfloat16* __restrict__ wlo,
    float* __restrict__ out, int first)
{
    const int i = blockIdx.x;
    const int len = i + 1;
    const int tid = threadIdx.x;

    __shared__ float row[NTOK];
    __shared__ float red[256];

    const float* wr = w + (size_t)i * NTOK;

    float m = -3.4e38f;
    for (int j = tid; j < len; j += 256) {
        float v = wr[j];
        row[j] = v;
        m = fmaxf(m, v);
    }
    red[tid] = m;
    __syncthreads();
#pragma unroll
    for (int s = 128; s > 0; s >>= 1) {
        if (tid < s) red[tid] = fmaxf(red[tid], red[tid + s]);
        __syncthreads();
    }
    m = red[0];
    __syncthreads();

    float sum = 0.f;
    for (int j = tid; j < len; j += 256) {
        float e = __expf(row[j] - m);   // arg <= 0, bounded
        row[j] = e;
        sum += e;
    }
    red[tid] = sum;
    __syncthreads();
#pragma unroll
    for (int s = 128; s > 0; s >>= 1) {
        if (tid < s) red[tid] += red[tid + s];
        __syncthreads();
    }
    const float inv = 1.0f / red[0];

    float* outr = out + (size_t)i * NTOK;
    __nv_bfloat16* hr = whi + (size_t)i * NTOK;
    __nv_bfloat16* lr = wlo + (size_t)i * NTOK;
    for (int j = tid; j < NTOK; j += 256) {
        float v = (j < len) ? row[j] * inv : 0.f;
        float h = __bfloat162float(__float2bfloat16_rn(v));
        hr[j] = __float2bfloat16_rn(v);
        lr[j] = __float2bfloat16_rn(v - h);
        if (first) outr[j] = 0.25f * v;
        else       outr[j] += 0.25f * v;
    }
}

// ---------------------------------------------------------------------------
// Transpose v slice of qkv (hi & lo):  vT[c, r] = qkv[r, 2E + c]
// ---------------------------------------------------------------------------
__global__ void transpose_v(const __nv_bfloat16* __restrict__ qh,
                            const __nv_bfloat16* __restrict__ ql,
                            __nv_bfloat16* __restrict__ th,
                            __nv_bfloat16* __restrict__ tl)
{
    __shared__ __nv_bfloat16 sh[32][33];
    __shared__ __nv_bfloat16 sl[32][33];
    const int c0 = blockIdx.x * 32, r0 = blockIdx.y * 32;
    const int tx = threadIdx.x, ty = threadIdx.y;
#pragma unroll
    for (int k = 0; k < 4; k++) {
        int r = ty + k * 8;
        size_t src = (size_t)(r0 + r) * (3 * EDIM) + 2 * EDIM + c0 + tx;
        sh[r][tx] = qh[src];
        sl[r][tx] = ql[src];
    }
    __syncthreads();
#pragma unroll
    for (int k = 0; k < 4; k++) {
        int cc = ty + k * 8;
        size_t dst = (size_t)(c0 + cc) * NTOK + r0 + tx;
        th[dst] = sh[tx][cc];
        tl[dst] = sl[tx][cc];
    }
}

// fp32 -> bf16 hi/lo split (vectorized by 4)
__global__ void split_bf16(const float* __restrict__ src,
                           __nv_bfloat16* __restrict__ hi,
                           __nv_bfloat16* __restrict__ lo, int n4)
{
    int idx = blockIdx.x * blockDim.x + threadIdx.x;
    if (idx >= n4) return;
    float4 v = ((const float4*)src)[idx];
    float h0 = __bfloat162float(__float2bfloat16_rn(v.x));
    float h1 = __bfloat162float(__float2bfloat16_rn(v.y));
    float h2 = __bfloat162float(__float2bfloat16_rn(v.z));
    float h3 = __bfloat162float(__float2bfloat16_rn(v.w));
    uint2 ph, pl;
    ph.x = pack2bf(h0, h1);             ph.y = pack2bf(h2, h3);
    pl.x = pack2bf(v.x - h0, v.y - h1); pl.y = pack2bf(v.z - h2, v.w - h3);
    ((uint2*)hi)[idx] = ph;
    ((uint2*)lo)[idx] = pl;
}

// ---------------------------------------------------------------------------
extern "C" void kernel_launch(void* const* d_in, const int* in_sizes, int n_in,
                              void* d_out, int out_size)
{
    const float* mentions = (const float*)d_in[0];  // [2048,1024]
    const float* Wqkv     = (const float*)d_in[1];  // [4,3072,1024]
    const float* bqkv     = (const float*)d_in[2];  // [4,3072]
    const float* Wo       = (const float*)d_in[3];  // [4,1024,1024]
    const float* bo       = (const float*)d_in[4];  // [4,1024]
    float* out            = (float*)d_out;          // [2048,2048]

    __nv_bfloat16 *xhi, *xlo, *qkvhi, *qkvlo, *whi, *wlo, *vThi, *vTlo,
                  *wvhi, *wvlo, *Wqhi, *Wqlo, *Wohi, *Wolo;
    float* w;
    cudaGetSymbolAddress((void**)&xhi, g_xhi);     cudaGetSymbolAddress((void**)&xlo, g_xlo);
    cudaGetSymbolAddress((void**)&qkvhi, g_qkvhi); cudaGetSymbolAddress((void**)&qkvlo, g_qkvlo);
    cudaGetSymbolAddress((void**)&w, g_w);
    cudaGetSymbolAddress((void**)&whi, g_whi);     cudaGetSymbolAddress((void**)&wlo, g_wlo);
    cudaGetSymbolAddress((void**)&vThi, g_vThi);   cudaGetSymbolAddress((void**)&vTlo, g_vTlo);
    cudaGetSymbolAddress((void**)&wvhi, g_wvhi);   cudaGetSymbolAddress((void**)&wvlo, g_wvlo);
    cudaGetSymbolAddress((void**)&Wqhi, g_Wqkvhi); cudaGetSymbolAddress((void**)&Wqlo, g_Wqkvlo);
    cudaGetSymbolAddress((void**)&Wohi, g_Wohi);   cudaGetSymbolAddress((void**)&Wolo, g_Wolo);

    cudaFuncSetAttribute(gemm_mma<2, false, false>,
                         cudaFuncAttributeMaxDynamicSharedMemorySize, SMEM_BYTES);
    cudaFuncSetAttribute(gemm_mma<0, true, false>,
                         cudaFuncAttributeMaxDynamicSharedMemorySize, SMEM_BYTES);
    cudaFuncSetAttribute(gemm_mma<1, false, true>,
                         cudaFuncAttributeMaxDynamicSharedMemorySize, SMEM_BYTES);

    const float scale = 1.0f / 32.0f;   // 1/sqrt(1024)

    // Split weights + input activations into bf16 hi/lo
    {
        int n4 = NLAYER * 3 * EDIM * EDIM / 4;
        split_bf16<<<(n4 + 255) / 256, 256>>>(Wqkv, Wqhi, Wqlo, n4);
        n4 = NLAYER * EDIM * EDIM / 4;
        split_bf16<<<(n4 + 255) / 256, 256>>>(Wo, Wohi, Wolo, n4);
        n4 = NTOK * EDIM / 4;
        split_bf16<<<(n4 + 255) / 256, 256>>>(mentions, xhi, xlo, n4);
    }

    for (int l = 0; l < NLAYER; l++) {
        const __nv_bfloat16* Wqh = Wqhi + (size_t)l * 3 * EDIM * EDIM;
        const __nv_bfloat16* Wql = Wqlo + (size_t)l * 3 * EDIM * EDIM;
        const __nv_bfloat16* Woh = Wohi + (size_t)l * EDIM * EDIM;
        const __nv_bfloat16* Wol = Wolo + (size_t)l * EDIM * EDIM;
        const float* bq = bqkv + (size_t)l * 3 * EDIM;
        const float* bl = bo   + (size_t)l * EDIM;

        // qkv = x @ Wqkv^T + bqkv      -> bf16 hi/lo [2048,3072]
        gemm_mma<2, false, false><<<dim3(24, 16), 256, SMEM_BYTES>>>(
            xhi, xlo, EDIM, Wqh, Wql, EDIM,
            nullptr, qkvhi, qkvlo, 3 * EDIM, bq, EDIM, 1.0f);

        // scores = scale * q @ k^T     -> fp32 [2048,2048], lower blocks only
        gemm_mma<0, true, false><<<dim3(16, 16), 256, SMEM_BYTES>>>(
            qkvhi, qkvlo, 3 * EDIM, qkvhi + EDIM, qkvlo + EDIM, 3 * EDIM,
            w, nullptr, nullptr, NTOK, nullptr, EDIM, scale);

        // softmax -> w hi/lo, accumulate 0.25*w into out
        softmax_causal_acc<<<NTOK, 256>>>(w, whi, wlo, out, l == 0 ? 1 : 0);

        // vT = transpose of v slice
        transpose_v<<<dim3(EDIM / 32, NTOK / 32), dim3(32, 8)>>>(qkvhi, qkvlo, vThi, vTlo);

        // wv = w @ v                    -> bf16 hi/lo [2048,1024]  (K limited)
        gemm_mma<1, false, true><<<dim3(8, 16), 256, SMEM_BYTES>>>(
            whi, wlo, NTOK, vThi, vTlo, NTOK,
            nullptr, wvhi, wvlo, EDIM, nullptr, NTOK, 1.0f);

        // x = wv @ Wo^T + bo            -> bf16 hi/lo [2048,1024]
        gemm_mma<2, false, false><<<dim3(8, 16), 256, SMEM_BYTES>>>(
            wvhi, wvlo, EDIM, Woh, Wol, EDIM,
            nullptr, xhi, xlo, EDIM, bl, EDIM, 1.0f);
    }
}

// round 6
// speedup vs baseline: 1.1705x; 1.1705x over previous
#include <cuda_runtime.h>
#include <cuda_bf16.h>
#include <stdint.h>
#include <math.h>

#define NTOK 2048
#define EDIM 1024
#define NLAYER 4

// ---------------------------------------------------------------------------
// Scratch (device globals — allocation is forbidden)
// ---------------------------------------------------------------------------
__device__ __nv_bfloat16 g_xhi[NTOK * EDIM], g_xlo[NTOK * EDIM];
__device__ __nv_bfloat16 g_qkvhi[NTOK * 3 * EDIM], g_qkvlo[NTOK * 3 * EDIM];
__device__ float         g_p0[NTOK * 3 * EDIM];   // split-K partial 0 (24MB, reused)
__device__ float         g_p1[NTOK * 3 * EDIM];   // split-K partial 1
__device__ __nv_bfloat16 g_whi[NTOK * NTOK], g_wlo[NTOK * NTOK];
__device__ __nv_bfloat16 g_vThi[EDIM * NTOK], g_vTlo[EDIM * NTOK];
__device__ __nv_bfloat16 g_wvhi[NTOK * EDIM], g_wvlo[NTOK * EDIM];
__device__ __nv_bfloat16 g_Wqkvhi[NLAYER * 3 * EDIM * EDIM], g_Wqkvlo[NLAYER * 3 * EDIM * EDIM];
__device__ __nv_bfloat16 g_Wohi[NLAYER * EDIM * EDIM], g_Wolo[NLAYER * EDIM * EDIM];

// ---------------------------------------------------------------------------
// Helpers
// ---------------------------------------------------------------------------
__device__ __forceinline__ uint32_t s2u(const void* p) {
    uint32_t a;
    asm("{ .reg .u64 t; cvta.to.shared.u64 t, %1; cvt.u32.u64 %0, t; }" : "=r"(a) : "l"(p));
    return a;
}
#define CPA(sm, gp) \
    asm volatile("cp.async.cg.shared.global [%0], [%1], 16;" :: "r"(sm), "l"(gp))
#define CPA_COMMIT() asm volatile("cp.async.commit_group;")
#define CPA_WAIT2()  asm volatile("cp.async.wait_group 2;")

#define LDSM4(r0, r1, r2, r3, addr)                                          \
    asm volatile("ldmatrix.sync.aligned.m8n8.x4.shared.b16 {%0,%1,%2,%3}, [%4];" \
                 : "=r"(r0), "=r"(r1), "=r"(r2), "=r"(r3) : "r"(addr))

__device__ __forceinline__ void mma16816(float* c, const uint32_t* a, const uint32_t* b) {
    asm volatile(
        "mma.sync.aligned.m16n8k16.row.col.f32.bf16.bf16.f32 "
        "{%0,%1,%2,%3}, {%4,%5,%6,%7}, {%8,%9}, {%0,%1,%2,%3};"
        : "+f"(c[0]), "+f"(c[1]), "+f"(c[2]), "+f"(c[3])
        : "r"(a[0]), "r"(a[1]), "r"(a[2]), "r"(a[3]), "r"(b[0]), "r"(b[1]));
}

__device__ __forceinline__ uint32_t pack2bf(float a, float b) {
    __nv_bfloat162 t = __floats2bfloat162_rn(a, b);
    return *reinterpret_cast<uint32_t*>(&t);
}

// SMEM: 4 stages; stage = 4 tiles (Ahi, Alo, Bhi, Blo) of 128 rows x 16 bf16,
// 48B pitch (banks 12r mod 32 all distinct for r=0..7 -> conflict-free ldmatrix;
// 48 is a multiple of 16 -> cp.async 16B alignment holds).
#define TILE_B   6144          // 128 * 48
#define STAGE_B  24576         // 4 tiles
#define SMEM_BYTES (4 * STAGE_B)   // 98304 -> 2 CTAs/SM

// ---------------------------------------------------------------------------
// Split-K (x2) tensor-core NT GEMM, fused 3-pass bf16 hi/lo split:
//   partial[kz] = sum_{k in half kz} Ahi*Bhi + Ahi*Blo + Alo*Bhi  (fp32 out)
//   CSKIP: skip blocks strictly above diagonal;  KLIM: Keff = (by+1)*128
// 4-stage cp.async pipeline, ONE __syncthreads per chunk (K-chunk = 16).
// ---------------------------------------------------------------------------
template<bool CSKIP, bool KLIM>
__global__ void __launch_bounds__(256, 2) gemm_mma(
    const __nv_bfloat16* __restrict__ Ahi, const __nv_bfloat16* __restrict__ Alo, int lda,
    const __nv_bfloat16* __restrict__ Bhi, const __nv_bfloat16* __restrict__ Blo, int ldb,
    float* __restrict__ Cf0, float* __restrict__ Cf1, int ldc,
    int K, float alpha)
{
    const int bx = blockIdx.x, by = blockIdx.y, kz = blockIdx.z;
    if (CSKIP && bx > by) return;
    const int Keff = KLIM ? min(K, (by + 1) * 128) : K;
    const int half = Keff >> 1;            // always a multiple of 64
    const int k0   = kz ? half : 0;
    const int nch  = half / 16;            // >= 4 in all uses

    float* __restrict__ Cp = kz ? Cf1 : Cf0;

    extern __shared__ __align__(128) char smem[];
    const uint32_t sb = s2u(smem);

    const int tid  = threadIdx.x;
    const int wid  = tid >> 5, lane = tid & 31;
    const int wm   = (wid & 1) * 64;       // warp m offset (2 warps)
    const int wn   = (wid >> 1) * 32;      // warp n offset (4 warps)

    const __nv_bfloat16* Abh = Ahi + (size_t)(by * 128) * lda;
    const __nv_bfloat16* Abl = Alo + (size_t)(by * 128) * lda;
    const __nv_bfloat16* Bbh = Bhi + (size_t)(bx * 128) * ldb;
    const __nv_bfloat16* Bbl = Blo + (size_t)(bx * 128) * ldb;

    // ldmatrix per-lane address components
    const uint32_t a_row = lane & 15;
    const uint32_t a_k   = (lane >> 4) * 16;
    const uint32_t b_row = (lane & 7) + (lane >> 4) * 8;
    const uint32_t b_k   = ((lane >> 3) & 1) * 16;

    float acc[4][4][4];
#pragma unroll
    for (int i = 0; i < 4; i++)
#pragma unroll
        for (int j = 0; j < 4; j++)
#pragma unroll
            for (int r = 0; r < 4; r++) acc[i][j][r] = 0.f;

    // per-thread loader slot: one 16B vector per tile
    const int lrow = tid >> 1;             // 0..127
    const int lc   = tid & 1;              // 0..1
    const uint32_t lso = (uint32_t)lrow * 48 + lc * 16;
    const size_t   lga = (size_t)lrow * lda + lc * 8;
    const size_t   lgb = (size_t)lrow * ldb + lc * 8;

    auto load_stage = [&](int stage, int kt) {
        uint32_t base = sb + (uint32_t)stage * STAGE_B + lso;
        CPA(base,              Abh + lga + kt);
        CPA(base + TILE_B,     Abl + lga + kt);
        CPA(base + 2 * TILE_B, Bbh + lgb + kt);
        CPA(base + 3 * TILE_B, Bbl + lgb + kt);
    };

    // prologue: stages 0..2 (nch >= 4 always)
#pragma unroll
    for (int s = 0; s < 3; s++) { load_stage(s, k0 + s * 16); CPA_COMMIT(); }

    for (int c = 0; c < nch; c++) {
        CPA_WAIT2();            // chunk c's group complete (<=2 newer pending)
        __syncthreads();        // data visible + all warps done with stage c-1
        // safe now to overwrite stage (c+3)&3 == (c-1)&3
        if (c + 3 < nch) load_stage((c + 3) & 3, k0 + (c + 3) * 16);
        CPA_COMMIT();           // uniform commit keeps group counting simple

        const uint32_t base = sb + (uint32_t)(c & 3) * STAGE_B;

        uint32_t bh[8], bl[8];
        {
            uint32_t bb = base + 2 * TILE_B + (wn + b_row) * 48 + b_k;
            LDSM4(bh[0], bh[1], bh[2], bh[3], bb);
            LDSM4(bh[4], bh[5], bh[6], bh[7], bb + 16 * 48);
            LDSM4(bl[0], bl[1], bl[2], bl[3], bb + TILE_B);
            LDSM4(bl[4], bl[5], bl[6], bl[7], bb + TILE_B + 16 * 48);
        }
#pragma unroll
        for (int mf = 0; mf < 4; mf++) {
            uint32_t ah[4], al[4];
            uint32_t ab = base + (wm + mf * 16 + a_row) * 48 + a_k;
            LDSM4(ah[0], ah[1], ah[2], ah[3], ab);
            LDSM4(al[0], al[1], al[2], al[3], ab + TILE_B);
#pragma unroll
            for (int nf = 0; nf < 4; nf++)
                mma16816(acc[mf][nf], ah, bh + nf * 2);   // hi*hi
#pragma unroll
            for (int nf = 0; nf < 4; nf++)
                mma16816(acc[mf][nf], ah, bl + nf * 2);   // hi*lo
#pragma unroll
            for (int nf = 0; nf < 4; nf++)
                mma16816(acc[mf][nf], al, bh + nf * 2);   // lo*hi
        }
    }

    // ---- epilogue: fp32 partial ----
#pragma unroll
    for (int mf = 0; mf < 4; mf++) {
#pragma unroll
        for (int nf = 0; nf < 4; nf++) {
            const float* cc = acc[mf][nf];
            int row0 = by * 128 + wm + mf * 16 + (lane >> 2);
            int col  = bx * 128 + wn + nf * 8 + (lane & 3) * 2;
            float2 v0 = make_float2(alpha * cc[0], alpha * cc[1]);
            float2 v1 = make_float2(alpha * cc[2], alpha * cc[3]);
            *(float2*)(Cp + (size_t)row0 * ldc + col) = v0;
            *(float2*)(Cp + (size_t)(row0 + 8) * ldc + col) = v1;
        }
    }
}

// ---------------------------------------------------------------------------
// combine split-K partials: v = p0 + p1 (+ bias[col]); write bf16 hi/lo
// ---------------------------------------------------------------------------
__global__ void combine_split(const float* __restrict__ p0, const float* __restrict__ p1,
                              const float* __restrict__ bias,
                              __nv_bfloat16* __restrict__ hi, __nv_bfloat16* __restrict__ lo,
                              int ncols, int n4)
{
    int idx = blockIdx.x * blockDim.x + threadIdx.x;
    if (idx >= n4) return;
    float4 a = ((const float4*)p0)[idx];
    float4 b = ((const float4*)p1)[idx];
    float v0 = a.x + b.x, v1 = a.y + b.y, v2 = a.z + b.z, v3 = a.w + b.w;
    if (bias) {
        int col = (idx * 4) % ncols;     // ncols multiple of 4 -> col aligned
        v0 += bias[col]; v1 += bias[col + 1]; v2 += bias[col + 2]; v3 += bias[col + 3];
    }
    float h0 = __bfloat162float(__float2bfloat16_rn(v0));
    float h1 = __bfloat162float(__float2bfloat16_rn(v1));
    float h2 = __bfloat162float(__float2bfloat16_rn(v2));
    float h3 = __bfloat162float(__float2bfloat16_rn(v3));
    uint2 ph, pl;
    ph.x = pack2bf(h0, h1);          ph.y = pack2bf(h2, h3);
    pl.x = pack2bf(v0 - h0, v1 - h1); pl.y = pack2bf(v2 - h2, v3 - h3);
    ((uint2*)hi)[idx] = ph;
    ((uint2*)lo)[idx] = pl;
}

// ---------------------------------------------------------------------------
// Causal softmax over row i (len = i+1); scores = p0 + p1 (split-K partials);
// writes bf16 hi/lo weights (zero-padded) and accumulates 0.25*w into out.
// ---------------------------------------------------------------------------
__global__ __launch_bounds__(256) void softmax_causal_acc(
    const float* __restrict__ w0, const float* __restrict__ w1,
    __nv_bfloat16* __restrict__ whi, __nv_bfloat16* __restrict__ wlo,
    float* __restrict__ out, int first)
{
    const int i = blockIdx.x;
    const int len = i + 1;
    const int tid = threadIdx.x;

    __shared__ float row[NTOK];
    __shared__ float red[256];

    const float* wr0 = w0 + (size_t)i * NTOK;
    const float* wr1 = w1 + (size_t)i * NTOK;

    float m = -3.4e38f;
    for (int j = tid; j < len; j += 256) {
        float v = wr0[j] + wr1[j];
        row[j] = v;
        m = fmaxf(m, v);
    }
    red[tid] = m;
    __syncthreads();
#pragma unroll
    for (int s = 128; s > 0; s >>= 1) {
        if (tid < s) red[tid] = fmaxf(red[tid], red[tid + s]);
        __syncthreads();
    }
    m = red[0];
    __syncthreads();

    float sum = 0.f;
    for (int j = tid; j < len; j += 256) {
        float e = __expf(row[j] - m);   // arg <= 0, bounded
        row[j] = e;
        sum += e;
    }
    red[tid] = sum;
    __syncthreads();
#pragma unroll
    for (int s = 128; s > 0; s >>= 1) {
        if (tid < s) red[tid] += red[tid + s];
        __syncthreads();
    }
    const float inv = 1.0f / red[0];

    float* outr = out + (size_t)i * NTOK;
    __nv_bfloat16* hr = whi + (size_t)i * NTOK;
    __nv_bfloat16* lr = wlo + (size_t)i * NTOK;
    for (int j = tid; j < NTOK; j += 256) {
        float v = (j < len) ? row[j] * inv : 0.f;
        float h = __bfloat162float(__float2bfloat16_rn(v));
        hr[j] = __float2bfloat16_rn(v);
        lr[j] = __float2bfloat16_rn(v - h);
        if (first) outr[j] = 0.25f * v;
        else       outr[j] += 0.25f * v;
    }
}

// ---------------------------------------------------------------------------
// Transpose v slice of qkv (hi & lo):  vT[c, r] = qkv[r, 2E + c]
// ---------------------------------------------------------------------------
__global__ void transpose_v(const __nv_bfloat16* __restrict__ qh,
                            const __nv_bfloat16* __restrict__ ql,
                            __nv_bfloat16* __restrict__ th,
                            __nv_bfloat16* __restrict__ tl)
{
    __shared__ __nv_bfloat16 sh[32][33];
    __shared__ __nv_bfloat16 sl[32][33];
    const int c0 = blockIdx.x * 32, r0 = blockIdx.y * 32;
    const int tx = threadIdx.x, ty = threadIdx.y;
#pragma unroll
    for (int k = 0; k < 4; k++) {
        int r = ty + k * 8;
        size_t src = (size_t)(r0 + r) * (3 * EDIM) + 2 * EDIM + c0 + tx;
        sh[r][tx] = qh[src];
        sl[r][tx] = ql[src];
    }
    __syncthreads();
#pragma unroll
    for (int k = 0; k < 4; k++) {
        int cc = ty + k * 8;
        size_t dst = (size_t)(c0 + cc) * NTOK + r0 + tx;
        th[dst] = sh[tx][cc];
        tl[dst] = sl[tx][cc];
    }
}

// fp32 -> bf16 hi/lo split (vectorized by 4)
__global__ void split_bf16(const float* __restrict__ src,
                           __nv_bfloat16* __restrict__ hi,
                           __nv_bfloat16* __restrict__ lo, int n4)
{
    int idx = blockIdx.x * blockDim.x + threadIdx.x;
    if (idx >= n4) return;
    float4 v = ((const float4*)src)[idx];
    float h0 = __bfloat162float(__float2bfloat16_rn(v.x));
    float h1 = __bfloat162float(__float2bfloat16_rn(v.y));
    float h2 = __bfloat162float(__float2bfloat16_rn(v.z));
    float h3 = __bfloat162float(__float2bfloat16_rn(v.w));
    uint2 ph, pl;
    ph.x = pack2bf(h0, h1);             ph.y = pack2bf(h2, h3);
    pl.x = pack2bf(v.x - h0, v.y - h1); pl.y = pack2bf(v.z - h2, v.w - h3);
    ((uint2*)hi)[idx] = ph;
    ((uint2*)lo)[idx] = pl;
}

// ---------------------------------------------------------------------------
extern "C" void kernel_launch(void* const* d_in, const int* in_sizes, int n_in,
                              void* d_out, int out_size)
{
    const float* mentions = (const float*)d_in[0];  // [2048,1024]
    const float* Wqkv     = (const float*)d_in[1];  // [4,3072,1024]
    const float* bqkv     = (const float*)d_in[2];  // [4,3072]
    const float* Wo       = (const float*)d_in[3];  // [4,1024,1024]
    const float* bo       = (const float*)d_in[4];  // [4,1024]
    float* out            = (float*)d_out;          // [2048,2048]

    __nv_bfloat16 *xhi, *xlo, *qkvhi, *qkvlo, *whi, *wlo, *vThi, *vTlo,
                  *wvhi, *wvlo, *Wqhi, *Wqlo, *Wohi, *Wolo;
    float *p0, *p1;
    cudaGetSymbolAddress((void**)&xhi, g_xhi);     cudaGetSymbolAddress((void**)&xlo, g_xlo);
    cudaGetSymbolAddress((void**)&qkvhi, g_qkvhi); cudaGetSymbolAddress((void**)&qkvlo, g_qkvlo);
    cudaGetSymbolAddress((void**)&p0, g_p0);       cudaGetSymbolAddress((void**)&p1, g_p1);
    cudaGetSymbolAddress((void**)&whi, g_whi);     cudaGetSymbolAddress((void**)&wlo, g_wlo);
    cudaGetSymbolAddress((void**)&vThi, g_vThi);   cudaGetSymbolAddress((void**)&vTlo, g_vTlo);
    cudaGetSymbolAddress((void**)&wvhi, g_wvhi);   cudaGetSymbolAddress((void**)&wvlo, g_wvlo);
    cudaGetSymbolAddress((void**)&Wqhi, g_Wqkvhi); cudaGetSymbolAddress((void**)&Wqlo, g_Wqkvlo);
    cudaGetSymbolAddress((void**)&Wohi, g_Wohi);   cudaGetSymbolAddress((void**)&Wolo, g_Wolo);

    cudaFuncSetAttribute(gemm_mma<false, false>,
                         cudaFuncAttributeMaxDynamicSharedMemorySize, SMEM_BYTES);
    cudaFuncSetAttribute(gemm_mma<true, false>,
                         cudaFuncAttributeMaxDynamicSharedMemorySize, SMEM_BYTES);
    cudaFuncSetAttribute(gemm_mma<false, true>,
                         cudaFuncAttributeMaxDynamicSharedMemorySize, SMEM_BYTES);

    const float scale = 1.0f / 32.0f;   // 1/sqrt(1024)

    // Split weights + input activations into bf16 hi/lo
    {
        int n4 = NLAYER * 3 * EDIM * EDIM / 4;
        split_bf16<<<(n4 + 255) / 256, 256>>>(Wqkv, Wqhi, Wqlo, n4);
        n4 = NLAYER * EDIM * EDIM / 4;
        split_bf16<<<(n4 + 255) / 256, 256>>>(Wo, Wohi, Wolo, n4);
        n4 = NTOK * EDIM / 4;
        split_bf16<<<(n4 + 255) / 256, 256>>>(mentions, xhi, xlo, n4);
    }

    for (int l = 0; l < NLAYER; l++) {
        const __nv_bfloat16* Wqh = Wqhi + (size_t)l * 3 * EDIM * EDIM;
        const __nv_bfloat16* Wql = Wqlo + (size_t)l * 3 * EDIM * EDIM;
        const __nv_bfloat16* Woh = Wohi + (size_t)l * EDIM * EDIM;
        const __nv_bfloat16* Wol = Wolo + (size_t)l * EDIM * EDIM;
        const float* bq = bqkv + (size_t)l * 3 * EDIM;
        const float* bl = bo   + (size_t)l * EDIM;

        // qkv partials = x @ Wqkv^T   (split-K x2)  [2048,3072] fp32
        gemm_mma<false, false><<<dim3(24, 16, 2), 256, SMEM_BYTES>>>(
            xhi, xlo, EDIM, Wqh, Wql, EDIM, p0, p1, 3 * EDIM, EDIM, 1.0f);
        // qkv = p0 + p1 + bqkv -> bf16 hi/lo
        combine_split<<<(NTOK * 3 * EDIM / 4 + 255) / 256, 256>>>(
            p0, p1, bq, qkvhi, qkvlo, 3 * EDIM, NTOK * 3 * EDIM / 4);

        // scores partials = scale * q @ k^T  (split-K x2, lower blocks only)
        gemm_mma<true, false><<<dim3(16, 16, 2), 256, SMEM_BYTES>>>(
            qkvhi, qkvlo, 3 * EDIM, qkvhi + EDIM, qkvlo + EDIM, 3 * EDIM,
            p0, p1, NTOK, EDIM, scale);

        // softmax (sums partials) -> w hi/lo, accumulate 0.25*w into out
        softmax_causal_acc<<<NTOK, 256>>>(p0, p1, whi, wlo, out, l == 0 ? 1 : 0);

        // vT = transpose of v slice
        transpose_v<<<dim3(EDIM / 32, NTOK / 32), dim3(32, 8)>>>(qkvhi, qkvlo, vThi, vTlo);

        // wv partials = w @ v  (split-K x2, K limited per row-block)
        gemm_mma<false, true><<<dim3(8, 16, 2), 256, SMEM_BYTES>>>(
            whi, wlo, NTOK, vThi, vTlo, NTOK, p0, p1, EDIM, NTOK, 1.0f);
        combine_split<<<(NTOK * EDIM / 4 + 255) / 256, 256>>>(
            p0, p1, nullptr, wvhi, wvlo, EDIM, NTOK * EDIM / 4);

        // x partials = wv @ Wo^T  (split-K x2)
        gemm_mma<false, false><<<dim3(8, 16, 2), 256, SMEM_BYTES>>>(
            wvhi, wvlo, EDIM, Woh, Wol, EDIM, p0, p1, EDIM, EDIM, 1.0f);
        combine_split<<<(NTOK * EDIM / 4 + 255) / 256, 256>>>(
            p0, p1, bl, xhi, xlo, EDIM, NTOK * EDIM / 4);
    }
}

// round 7
// speedup vs baseline: 1.6846x; 1.4392x over previous
#include <cuda_runtime.h>
#include <cuda_fp16.h>
#include <stdint.h>
#include <math.h>

#define NTOK 2048
#define EDIM 1024
#define NLAYER 4

// ---------------------------------------------------------------------------
// Scratch (device globals — allocation is forbidden)
// Activations only need HI parts (they are always the A operand).
// Weights / k / v need hi+lo (B operand, 22-bit).
// ---------------------------------------------------------------------------
__device__ __half g_xhi[NTOK * EDIM];
__device__ __half g_qkvhi[NTOK * 3 * EDIM], g_qkvlo[NTOK * 3 * EDIM];
__device__ float  g_p0[NTOK * 3 * EDIM];   // split-K partial 0 (24MB, reused)
__device__ float  g_p1[NTOK * 3 * EDIM];   // split-K partial 1
__device__ __half g_whi[NTOK * NTOK];
__device__ __half g_vThi[EDIM * NTOK], g_vTlo[EDIM * NTOK];
__device__ __half g_wvhi[NTOK * EDIM];
__device__ __half g_Wqkvhi[NLAYER * 3 * EDIM * EDIM], g_Wqkvlo[NLAYER * 3 * EDIM * EDIM];
__device__ __half g_Wohi[NLAYER * EDIM * EDIM], g_Wolo[NLAYER * EDIM * EDIM];

// ---------------------------------------------------------------------------
// Helpers
// ---------------------------------------------------------------------------
__device__ __forceinline__ uint32_t s2u(const void* p) {
    uint32_t a;
    asm("{ .reg .u64 t; cvta.to.shared.u64 t, %1; cvt.u32.u64 %0, t; }" : "=r"(a) : "l"(p));
    return a;
}
#define CPA(sm, gp) \
    asm volatile("cp.async.cg.shared.global [%0], [%1], 16;" :: "r"(sm), "l"(gp))
#define CPA_COMMIT() asm volatile("cp.async.commit_group;")
#define CPA_WAIT2()  asm volatile("cp.async.wait_group 2;")

#define LDSM4(r0, r1, r2, r3, addr)                                          \
    asm volatile("ldmatrix.sync.aligned.m8n8.x4.shared.b16 {%0,%1,%2,%3}, [%4];" \
                 : "=r"(r0), "=r"(r1), "=r"(r2), "=r"(r3) : "r"(addr))

__device__ __forceinline__ void mma16816(float* c, const uint32_t* a, const uint32_t* b) {
    asm volatile(
        "mma.sync.aligned.m16n8k16.row.col.f32.f16.f16.f32 "
        "{%0,%1,%2,%3}, {%4,%5,%6,%7}, {%8,%9}, {%0,%1,%2,%3};"
        : "+f"(c[0]), "+f"(c[1]), "+f"(c[2]), "+f"(c[3])
        : "r"(a[0]), "r"(a[1]), "r"(a[2]), "r"(a[3]), "r"(b[0]), "r"(b[1]));
}

__device__ __forceinline__ uint32_t pack2h(float a, float b) {
    __half2 t = __floats2half2_rn(a, b);
    return *reinterpret_cast<uint32_t*>(&t);
}

// SMEM: 4 stages; stage = 3 tiles (Ahi, Bhi, Blo) of 128 rows x 16 fp16,
// 48B pitch (banks 12r mod 32 distinct for r=0..7 -> conflict-free ldmatrix).
#define TILE_B   6144          // 128 * 48
#define STAGE_B  18432         // 3 tiles
#define SMEM_BYTES (4 * STAGE_B)   // 73728 -> 2 CTAs/SM

// ---------------------------------------------------------------------------
// Split-K (x2) tensor-core NT GEMM, fused 2-pass fp16 split (B in hi+lo):
//   partial[kz] = sum_{k in half kz} Ahi*Bhi + Ahi*Blo   (fp32 out)
//   CSKIP: skip blocks strictly above diagonal;  KLIM: Keff = (by+1)*128
// 4-stage cp.async pipeline, ONE __syncthreads per chunk (K-chunk = 16).
// ---------------------------------------------------------------------------
template<bool CSKIP, bool KLIM>
__global__ void __launch_bounds__(256, 2) gemm_mma(
    const __half* __restrict__ Ahi, int lda,
    const __half* __restrict__ Bhi, const __half* __restrict__ Blo, int ldb,
    float* __restrict__ Cf0, float* __restrict__ Cf1, int ldc,
    int K, float alpha)
{
    const int bx = blockIdx.x, by = blockIdx.y, kz = blockIdx.z;
    if (CSKIP && bx > by) return;
    const int Keff = KLIM ? min(K, (by + 1) * 128) : K;
    const int half = Keff >> 1;            // multiple of 64
    const int k0   = kz ? half : 0;
    const int nch  = half / 16;            // >= 4 in all uses

    float* __restrict__ Cp = kz ? Cf1 : Cf0;

    extern __shared__ __align__(128) char smem[];
    const uint32_t sb = s2u(smem);

    const int tid  = threadIdx.x;
    const int wid  = tid >> 5, lane = tid & 31;
    const int wm   = (wid & 1) * 64;       // warp m offset (2 warps)
    const int wn   = (wid >> 1) * 32;      // warp n offset (4 warps)

    const __half* Abh = Ahi + (size_t)(by * 128) * lda;
    const __half* Bbh = Bhi + (size_t)(bx * 128) * ldb;
    const __half* Bbl = Blo + (size_t)(bx * 128) * ldb;

    // ldmatrix per-lane address components
    const uint32_t a_row = lane & 15;
    const uint32_t a_k   = (lane >> 4) * 16;
    const uint32_t b_row = (lane & 7) + (lane >> 4) * 8;
    const uint32_t b_k   = ((lane >> 3) & 1) * 16;

    float acc[4][4][4];
#pragma unroll
    for (int i = 0; i < 4; i++)
#pragma unroll
        for (int j = 0; j < 4; j++)
#pragma unroll
            for (int r = 0; r < 4; r++) acc[i][j][r] = 0.f;

    // per-thread loader slot: one 16B vector per tile
    const int lrow = tid >> 1;             // 0..127
    const int lc   = tid & 1;              // 0..1
    const uint32_t lso = (uint32_t)lrow * 48 + lc * 16;
    const size_t   lga = (size_t)lrow * lda + lc * 8;
    const size_t   lgb = (size_t)lrow * ldb + lc * 8;

    auto load_stage = [&](int stage, int kt) {
        uint32_t base = sb + (uint32_t)stage * STAGE_B + lso;
        CPA(base,              Abh + lga + kt);
        CPA(base + TILE_B,     Bbh + lgb + kt);
        CPA(base + 2 * TILE_B, Bbl + lgb + kt);
    };

    // prologue: stages 0..2
#pragma unroll
    for (int s = 0; s < 3; s++) { load_stage(s, k0 + s * 16); CPA_COMMIT(); }

    for (int c = 0; c < nch; c++) {
        CPA_WAIT2();            // chunk c's group complete (<=2 newer pending)
        __syncthreads();        // data visible + all warps done with stage c-1
        if (c + 3 < nch) load_stage((c + 3) & 3, k0 + (c + 3) * 16);
        CPA_COMMIT();           // uniform commit keeps group counting simple

        const uint32_t base = sb + (uint32_t)(c & 3) * STAGE_B;

        uint32_t bh[8], bl[8];
        {
            uint32_t bb = base + TILE_B + (wn + b_row) * 48 + b_k;
            LDSM4(bh[0], bh[1], bh[2], bh[3], bb);
            LDSM4(bh[4], bh[5], bh[6], bh[7], bb + 16 * 48);
            LDSM4(bl[0], bl[1], bl[2], bl[3], bb + TILE_B);
            LDSM4(bl[4], bl[5], bl[6], bl[7], bb + TILE_B + 16 * 48);
        }
#pragma unroll
        for (int mf = 0; mf < 4; mf++) {
            uint32_t ah[4];
            uint32_t ab = base + (wm + mf * 16 + a_row) * 48 + a_k;
            LDSM4(ah[0], ah[1], ah[2], ah[3], ab);
#pragma unroll
            for (int nf = 0; nf < 4; nf++)
                mma16816(acc[mf][nf], ah, bh + nf * 2);   // ah * bh
#pragma unroll
            for (int nf = 0; nf < 4; nf++)
                mma16816(acc[mf][nf], ah, bl + nf * 2);   // ah * bl
        }
    }

    // ---- epilogue: fp32 partial ----
#pragma unroll
    for (int mf = 0; mf < 4; mf++) {
#pragma unroll
        for (int nf = 0; nf < 4; nf++) {
            const float* cc = acc[mf][nf];
            int row0 = by * 128 + wm + mf * 16 + (lane >> 2);
            int col  = bx * 128 + wn + nf * 8 + (lane & 3) * 2;
            float2 v0 = make_float2(alpha * cc[0], alpha * cc[1]);
            float2 v1 = make_float2(alpha * cc[2], alpha * cc[3]);
            *(float2*)(Cp + (size_t)row0 * ldc + col) = v0;
            *(float2*)(Cp + (size_t)(row0 + 8) * ldc + col) = v1;
        }
    }
}

// ---------------------------------------------------------------------------
// combine split-K partials: v = p0 + p1 (+ bias[col]); write fp16 hi (+lo)
// ---------------------------------------------------------------------------
__global__ void combine_split(const float* __restrict__ p0, const float* __restrict__ p1,
                              const float* __restrict__ bias,
                              __half* __restrict__ hi, __half* __restrict__ lo,
                              int ncols, int n4)
{
    int idx = blockIdx.x * blockDim.x + threadIdx.x;
    if (idx >= n4) return;
    float4 a = ((const float4*)p0)[idx];
    float4 b = ((const float4*)p1)[idx];
    float v0 = a.x + b.x, v1 = a.y + b.y, v2 = a.z + b.z, v3 = a.w + b.w;
    if (bias) {
        int col = (idx * 4) % ncols;     // ncols multiple of 4 -> aligned
        v0 += bias[col]; v1 += bias[col + 1]; v2 += bias[col + 2]; v3 += bias[col + 3];
    }
    float h0 = __half2float(__float2half_rn(v0));
    float h1 = __half2float(__float2half_rn(v1));
    float h2 = __half2float(__float2half_rn(v2));
    float h3 = __half2float(__float2half_rn(v3));
    uint2 ph;
    ph.x = pack2h(h0, h1); ph.y = pack2h(h2, h3);
    ((uint2*)hi)[idx] = ph;
    if (lo) {
        uint2 pl;
        pl.x = pack2h(v0 - h0, v1 - h1); pl.y = pack2h(v2 - h2, v3 - h3);
        ((uint2*)lo)[idx] = pl;
    }
}

// ---------------------------------------------------------------------------
// Causal softmax over row i (len = i+1); scores = p0 + p1 (split-K partials);
// writes fp16 weights (zero-padded) and accumulates 0.25*w into out.
// ---------------------------------------------------------------------------
__global__ __launch_bounds__(256) void softmax_causal_acc(
    const float* __restrict__ w0, const float* __restrict__ w1,
    __half* __restrict__ whi, float* __restrict__ out, int first)
{
    const int i = blockIdx.x;
    const int len = i + 1;
    const int tid = threadIdx.x;

    __shared__ float row[NTOK];
    __shared__ float red[256];

    const float* wr0 = w0 + (size_t)i * NTOK;
    const float* wr1 = w1 + (size_t)i * NTOK;

    float m = -3.4e38f;
    for (int j = tid; j < len; j += 256) {
        float v = wr0[j] + wr1[j];
        row[j] = v;
        m = fmaxf(m, v);
    }
    red[tid] = m;
    __syncthreads();
#pragma unroll
    for (int s = 128; s > 0; s >>= 1) {
        if (tid < s) red[tid] = fmaxf(red[tid], red[tid + s]);
        __syncthreads();
    }
    m = red[0];
    __syncthreads();

    float sum = 0.f;
    for (int j = tid; j < len; j += 256) {
        float e = __expf(row[j] - m);   // arg <= 0, bounded
        row[j] = e;
        sum += e;
    }
    red[tid] = sum;
    __syncthreads();
#pragma unroll
    for (int s = 128; s > 0; s >>= 1) {
        if (tid < s) red[tid] += red[tid + s];
        __syncthreads();
    }
    const float inv = 1.0f / red[0];

    float* outr = out + (size_t)i * NTOK;
    __half* hr = whi + (size_t)i * NTOK;
    for (int j = tid; j < NTOK; j += 256) {
        float v = (j < len) ? row[j] * inv : 0.f;
        hr[j] = __float2half_rn(v);
        if (first) outr[j] = 0.25f * v;
        else       outr[j] += 0.25f * v;
    }
}

// ---------------------------------------------------------------------------
// Transpose v slice of qkv (hi & lo):  vT[c, r] = qkv[r, 2E + c]
// ---------------------------------------------------------------------------
__global__ void transpose_v(const __half* __restrict__ qh,
                            const __half* __restrict__ ql,
                            __half* __restrict__ th,
                            __half* __restrict__ tl)
{
    __shared__ __half sh[32][33];
    __shared__ __half sl[32][33];
    const int c0 = blockIdx.x * 32, r0 = blockIdx.y * 32;
    const int tx = threadIdx.x, ty = threadIdx.y;
#pragma unroll
    for (int k = 0; k < 4; k++) {
        int r = ty + k * 8;
        size_t src = (size_t)(r0 + r) * (3 * EDIM) + 2 * EDIM + c0 + tx;
        sh[r][tx] = qh[src];
        sl[r][tx] = ql[src];
    }
    __syncthreads();
#pragma unroll
    for (int k = 0; k < 4; k++) {
        int cc = ty + k * 8;
        size_t dst = (size_t)(c0 + cc) * NTOK + r0 + tx;
        th[dst] = sh[tx][cc];
        tl[dst] = sl[tx][cc];
    }
}

// fp32 -> fp16 hi (+lo) split (vectorized by 4)
__global__ void split_f16(const float* __restrict__ src,
                          __half* __restrict__ hi,
                          __half* __restrict__ lo, int n4)
{
    int idx = blockIdx.x * blockDim.x + threadIdx.x;
    if (idx >= n4) return;
    float4 v = ((const float4*)src)[idx];
    float h0 = __half2float(__float2half_rn(v.x));
    float h1 = __half2float(__float2half_rn(v.y));
    float h2 = __half2float(__float2half_rn(v.z));
    float h3 = __half2float(__float2half_rn(v.w));
    uint2 ph;
    ph.x = pack2h(h0, h1); ph.y = pack2h(h2, h3);
    ((uint2*)hi)[idx] = ph;
    if (lo) {
        uint2 pl;
        pl.x = pack2h(v.x - h0, v.y - h1); pl.y = pack2h(v.z - h2, v.w - h3);
        ((uint2*)lo)[idx] = pl;
    }
}

// ---------------------------------------------------------------------------
extern "C" void kernel_launch(void* const* d_in, const int* in_sizes, int n_in,
                              void* d_out, int out_size)
{
    const float* mentions = (const float*)d_in[0];  // [2048,1024]
    const float* Wqkv     = (const float*)d_in[1];  // [4,3072,1024]
    const float* bqkv     = (const float*)d_in[2];  // [4,3072]
    const float* Wo       = (const float*)d_in[3];  // [4,1024,1024]
    const float* bo       = (const float*)d_in[4];  // [4,1024]
    float* out            = (float*)d_out;          // [2048,2048]

    __half *xhi, *qkvhi, *qkvlo, *whi, *vThi, *vTlo, *wvhi,
           *Wqhi, *Wqlo, *Wohi, *Wolo;
    float *p0, *p1;
    cudaGetSymbolAddress((void**)&xhi, g_xhi);
    cudaGetSymbolAddress((void**)&qkvhi, g_qkvhi); cudaGetSymbolAddress((void**)&qkvlo, g_qkvlo);
    cudaGetSymbolAddress((void**)&p0, g_p0);       cudaGetSymbolAddress((void**)&p1, g_p1);
    cudaGetSymbolAddress((void**)&whi, g_whi);
    cudaGetSymbolAddress((void**)&vThi, g_vThi);   cudaGetSymbolAddress((void**)&vTlo, g_vTlo);
    cudaGetSymbolAddress((void**)&wvhi, g_wvhi);
    cudaGetSymbolAddress((void**)&Wqhi, g_Wqkvhi); cudaGetSymbolAddress((void**)&Wqlo, g_Wqkvlo);
    cudaGetSymbolAddress((void**)&Wohi, g_Wohi);   cudaGetSymbolAddress((void**)&Wolo, g_Wolo);

    cudaFuncSetAttribute(gemm_mma<false, false>,
                         cudaFuncAttributeMaxDynamicSharedMemorySize, SMEM_BYTES);
    cudaFuncSetAttribute(gemm_mma<true, false>,
                         cudaFuncAttributeMaxDynamicSharedMemorySize, SMEM_BYTES);
    cudaFuncSetAttribute(gemm_mma<false, true>,
                         cudaFuncAttributeMaxDynamicSharedMemorySize, SMEM_BYTES);

    const float scale = 1.0f / 32.0f;   // 1/sqrt(1024)

    // Split weights (hi+lo) and input activations (hi only) into fp16
    {
        int n4 = NLAYER * 3 * EDIM * EDIM / 4;
        split_f16<<<(n4 + 255) / 256, 256>>>(Wqkv, Wqhi, Wqlo, n4);
        n4 = NLAYER * EDIM * EDIM / 4;
        split_f16<<<(n4 + 255) / 256, 256>>>(Wo, Wohi, Wolo, n4);
        n4 = NTOK * EDIM / 4;
        split_f16<<<(n4 + 255) / 256, 256>>>(mentions, xhi, nullptr, n4);
    }

    for (int l = 0; l < NLAYER; l++) {
        const __half* Wqh = Wqhi + (size_t)l * 3 * EDIM * EDIM;
        const __half* Wql = Wqlo + (size_t)l * 3 * EDIM * EDIM;
        const __half* Woh = Wohi + (size_t)l * EDIM * EDIM;
        const __half* Wol = Wolo + (size_t)l * EDIM * EDIM;
        const float* bq = bqkv + (size_t)l * 3 * EDIM;
        const float* bl = bo   + (size_t)l * EDIM;

        // qkv partials = x @ Wqkv^T   (split-K x2)  [2048,3072] fp32
        gemm_mma<false, false><<<dim3(24, 16, 2), 256, SMEM_BYTES>>>(
            xhi, EDIM, Wqh, Wql, EDIM, p0, p1, 3 * EDIM, EDIM, 1.0f);
        // qkv = p0 + p1 + bqkv -> fp16 hi+lo (k, v used as B operand)
        combine_split<<<(NTOK * 3 * EDIM / 4 + 255) / 256, 256>>>(
            p0, p1, bq, qkvhi, qkvlo, 3 * EDIM, NTOK * 3 * EDIM / 4);

        // scores partials = scale * q @ k^T  (split-K x2, lower blocks only)
        gemm_mma<true, false><<<dim3(16, 16, 2), 256, SMEM_BYTES>>>(
            qkvhi, 3 * EDIM, qkvhi + EDIM, qkvlo + EDIM, 3 * EDIM,
            p0, p1, NTOK, EDIM, scale);

        // softmax (sums partials) -> w fp16, accumulate 0.25*w into out
        softmax_causal_acc<<<NTOK, 256>>>(p0, p1, whi, out, l == 0 ? 1 : 0);

        // vT = transpose of v slice (hi & lo)
        transpose_v<<<dim3(EDIM / 32, NTOK / 32), dim3(32, 8)>>>(qkvhi, qkvlo, vThi, vTlo);

        // wv partials = w @ v  (split-K x2, K limited per row-block)
        gemm_mma<false, true><<<dim3(8, 16, 2), 256, SMEM_BYTES>>>(
            whi, NTOK, vThi, vTlo, NTOK, p0, p1, EDIM, NTOK, 1.0f);
        combine_split<<<(NTOK * EDIM / 4 + 255) / 256, 256>>>(
            p0, p1, nullptr, wvhi, nullptr, EDIM, NTOK * EDIM / 4);

        // x partials = wv @ Wo^T  (split-K x2)
        gemm_mma<false, false><<<dim3(8, 16, 2), 256, SMEM_BYTES>>>(
            wvhi, EDIM, Woh, Wol, EDIM, p0, p1, EDIM, EDIM, 1.0f);
        combine_split<<<(NTOK * EDIM / 4 + 255) / 256, 256>>>(
            p0, p1, bl, xhi, nullptr, EDIM, NTOK * EDIM / 4);
    }
}

// round 8
// speedup vs baseline: 2.4928x; 1.4798x over previous
#include <cuda_runtime.h>
#include <cuda_fp16.h>
#include <stdint.h>
#include <math.h>

#define NTOK 2048
#define EDIM 1024
#define NLAYER 4

// ---------------------------------------------------------------------------
// Scratch (device globals — allocation is forbidden). Pure fp16 operands.
// ---------------------------------------------------------------------------
__device__ __half g_x[NTOK * EDIM];
__device__ __half g_qkv[NTOK * 3 * EDIM];
__device__ float  g_p0[NTOK * 3 * EDIM];   // split-K partial 0 (24MB, reused)
__device__ float  g_p1[NTOK * 3 * EDIM];   // split-K partial 1
__device__ __half g_wh[NTOK * NTOK];
__device__ __half g_vT[EDIM * NTOK];
__device__ __half g_wv[NTOK * EDIM];
__device__ __half g_Wqkv[NLAYER * 3 * EDIM * EDIM];
__device__ __half g_Wo[NLAYER * EDIM * EDIM];

// ---------------------------------------------------------------------------
// Helpers
// ---------------------------------------------------------------------------
__device__ __forceinline__ uint32_t s2u(const void* p) {
    uint32_t a;
    asm("{ .reg .u64 t; cvta.to.shared.u64 t, %1; cvt.u32.u64 %0, t; }" : "=r"(a) : "l"(p));
    return a;
}
#define CPA(sm, gp) \
    asm volatile("cp.async.cg.shared.global [%0], [%1], 16;" :: "r"(sm), "l"(gp))
#define CPA_COMMIT() asm volatile("cp.async.commit_group;")
#define CPA_WAIT2()  asm volatile("cp.async.wait_group 2;")

#define LDSM4(r0, r1, r2, r3, addr)                                          \
    asm volatile("ldmatrix.sync.aligned.m8n8.x4.shared.b16 {%0,%1,%2,%3}, [%4];" \
                 : "=r"(r0), "=r"(r1), "=r"(r2), "=r"(r3) : "r"(addr))

__device__ __forceinline__ void mma16816(float* c, const uint32_t* a, const uint32_t* b) {
    asm volatile(
        "mma.sync.aligned.m16n8k16.row.col.f32.f16.f16.f32 "
        "{%0,%1,%2,%3}, {%4,%5,%6,%7}, {%8,%9}, {%0,%1,%2,%3};"
        : "+f"(c[0]), "+f"(c[1]), "+f"(c[2]), "+f"(c[3])
        : "r"(a[0]), "r"(a[1]), "r"(a[2]), "r"(a[3]), "r"(b[0]), "r"(b[1]));
}

__device__ __forceinline__ uint32_t pack2h(float a, float b) {
    __half2 t = __floats2half2_rn(a, b);
    return *reinterpret_cast<uint32_t*>(&t);
}

// SMEM: 4 stages; stage = 2 tiles (A, B) of 128 rows x 16 fp16,
// 48B pitch (banks 12r mod 32 distinct for r=0..7 -> conflict-free ldmatrix).
#define TILE_B   6144          // 128 * 48
#define STAGE_B  12288         // 2 tiles
#define SMEM_BYTES (4 * STAGE_B)   // 49152

// ---------------------------------------------------------------------------
// Split-K (x2) tensor-core NT GEMM, single-pass fp16:
//   partial[kz] = sum_{k in half kz} A*B^T   (fp32 out)
//   CSKIP: skip blocks strictly above diagonal;  KLIM: Keff = (by+1)*128
// 4-stage cp.async pipeline, ONE __syncthreads per chunk (K-chunk = 16).
// ---------------------------------------------------------------------------
template<bool CSKIP, bool KLIM>
__global__ void __launch_bounds__(256, 2) gemm_mma(
    const __half* __restrict__ A, int lda,
    const __half* __restrict__ B, int ldb,
    float* __restrict__ Cf0, float* __restrict__ Cf1, int ldc,
    int K, float alpha)
{
    const int bx = blockIdx.x, by = blockIdx.y, kz = blockIdx.z;
    if (CSKIP && bx > by) return;
    const int Keff = KLIM ? min(K, (by + 1) * 128) : K;
    const int half = Keff >> 1;            // multiple of 64
    const int k0   = kz ? half : 0;
    const int nch  = half / 16;            // >= 4 in all uses

    float* __restrict__ Cp = kz ? Cf1 : Cf0;

    extern __shared__ __align__(128) char smem[];
    const uint32_t sb = s2u(smem);

    const int tid  = threadIdx.x;
    const int wid  = tid >> 5, lane = tid & 31;
    const int wm   = (wid & 1) * 64;       // warp m offset (2 warps)
    const int wn   = (wid >> 1) * 32;      // warp n offset (4 warps)

    const __half* Ab = A + (size_t)(by * 128) * lda;
    const __half* Bb = B + (size_t)(bx * 128) * ldb;

    // ldmatrix per-lane address components
    const uint32_t a_row = lane & 15;
    const uint32_t a_k   = (lane >> 4) * 16;
    const uint32_t b_row = (lane & 7) + (lane >> 4) * 8;
    const uint32_t b_k   = ((lane >> 3) & 1) * 16;

    float acc[4][4][4];
#pragma unroll
    for (int i = 0; i < 4; i++)
#pragma unroll
        for (int j = 0; j < 4; j++)
#pragma unroll
            for (int r = 0; r < 4; r++) acc[i][j][r] = 0.f;

    // per-thread loader slot: one 16B vector per tile
    const int lrow = tid >> 1;             // 0..127
    const int lc   = tid & 1;              // 0..1
    const uint32_t lso = (uint32_t)lrow * 48 + lc * 16;
    const size_t   lga = (size_t)lrow * lda + lc * 8;
    const size_t   lgb = (size_t)lrow * ldb + lc * 8;

    auto load_stage = [&](int stage, int kt) {
        uint32_t base = sb + (uint32_t)stage * STAGE_B + lso;
        CPA(base,          Ab + lga + kt);
        CPA(base + TILE_B, Bb + lgb + kt);
    };

    // prologue: stages 0..2
#pragma unroll
    for (int s = 0; s < 3; s++) { load_stage(s, k0 + s * 16); CPA_COMMIT(); }

    for (int c = 0; c < nch; c++) {
        CPA_WAIT2();            // chunk c's group complete (<=2 newer pending)
        __syncthreads();        // data visible + all warps done with stage c-1
        if (c + 3 < nch) load_stage((c + 3) & 3, k0 + (c + 3) * 16);
        CPA_COMMIT();           // uniform commit keeps group counting simple

        const uint32_t base = sb + (uint32_t)(c & 3) * STAGE_B;

        uint32_t bf[8];
        {
            uint32_t bb = base + TILE_B + (wn + b_row) * 48 + b_k;
            LDSM4(bf[0], bf[1], bf[2], bf[3], bb);
            LDSM4(bf[4], bf[5], bf[6], bf[7], bb + 16 * 48);
        }
#pragma unroll
        for (int mf = 0; mf < 4; mf++) {
            uint32_t ah[4];
            uint32_t ab = base + (wm + mf * 16 + a_row) * 48 + a_k;
            LDSM4(ah[0], ah[1], ah[2], ah[3], ab);
#pragma unroll
            for (int nf = 0; nf < 4; nf++)
                mma16816(acc[mf][nf], ah, bf + nf * 2);
        }
    }

    // ---- epilogue: fp32 partial ----
#pragma unroll
    for (int mf = 0; mf < 4; mf++) {
#pragma unroll
        for (int nf = 0; nf < 4; nf++) {
            const float* cc = acc[mf][nf];
            int row0 = by * 128 + wm + mf * 16 + (lane >> 2);
            int col  = bx * 128 + wn + nf * 8 + (lane & 3) * 2;
            float2 v0 = make_float2(alpha * cc[0], alpha * cc[1]);
            float2 v1 = make_float2(alpha * cc[2], alpha * cc[3]);
            *(float2*)(Cp + (size_t)row0 * ldc + col) = v0;
            *(float2*)(Cp + (size_t)(row0 + 8) * ldc + col) = v1;
        }
    }
}

// ---------------------------------------------------------------------------
// combine split-K partials: v = p0 + p1 (+ bias[col]); write fp16
// ---------------------------------------------------------------------------
__global__ void combine_split(const float* __restrict__ p0, const float* __restrict__ p1,
                              const float* __restrict__ bias,
                              __half* __restrict__ dst, int ncols, int n4)
{
    int idx = blockIdx.x * blockDim.x + threadIdx.x;
    if (idx >= n4) return;
    float4 a = ((const float4*)p0)[idx];
    float4 b = ((const float4*)p1)[idx];
    float v0 = a.x + b.x, v1 = a.y + b.y, v2 = a.z + b.z, v3 = a.w + b.w;
    if (bias) {
        int col = (idx * 4) % ncols;     // ncols multiple of 4 -> aligned
        v0 += bias[col]; v1 += bias[col + 1]; v2 += bias[col + 2]; v3 += bias[col + 3];
    }
    uint2 ph;
    ph.x = pack2h(v0, v1); ph.y = pack2h(v2, v3);
    ((uint2*)dst)[idx] = ph;
}

// ---------------------------------------------------------------------------
// Causal softmax over row i (len = i+1); scores = p0 + p1 (split-K partials);
// writes fp16 weights (zero-padded) and accumulates 0.25*w into out.
// ---------------------------------------------------------------------------
__global__ __launch_bounds__(256) void softmax_causal_acc(
    const float* __restrict__ w0, const float* __restrict__ w1,
    __half* __restrict__ wh, float* __restrict__ out, int first)
{
    const int i = blockIdx.x;
    const int len = i + 1;
    const int tid = threadIdx.x;

    __shared__ float row[NTOK];
    __shared__ float red[256];

    const float* wr0 = w0 + (size_t)i * NTOK;
    const float* wr1 = w1 + (size_t)i * NTOK;

    float m = -3.4e38f;
    for (int j = tid; j < len; j += 256) {
        float v = wr0[j] + wr1[j];
        row[j] = v;
        m = fmaxf(m, v);
    }
    red[tid] = m;
    __syncthreads();
#pragma unroll
    for (int s = 128; s > 0; s >>= 1) {
        if (tid < s) red[tid] = fmaxf(red[tid], red[tid + s]);
        __syncthreads();
    }
    m = red[0];
    __syncthreads();

    float sum = 0.f;
    for (int j = tid; j < len; j += 256) {
        float e = __expf(row[j] - m);   // arg <= 0, bounded
        row[j] = e;
        sum += e;
    }
    red[tid] = sum;
    __syncthreads();
#pragma unroll
    for (int s = 128; s > 0; s >>= 1) {
        if (tid < s) red[tid] += red[tid + s];
        __syncthreads();
    }
    const float inv = 1.0f / red[0];

    float* outr = out + (size_t)i * NTOK;
    __half* hr = wh + (size_t)i * NTOK;
    for (int j = tid; j < NTOK; j += 256) {
        float v = (j < len) ? row[j] * inv : 0.f;
        hr[j] = __float2half_rn(v);
        if (first) outr[j] = 0.25f * v;
        else       outr[j] += 0.25f * v;
    }
}

// ---------------------------------------------------------------------------
// Transpose v slice of qkv:  vT[c, r] = qkv[r, 2E + c]
// ---------------------------------------------------------------------------
__global__ void transpose_v(const __half* __restrict__ q,
                            __half* __restrict__ t)
{
    __shared__ __half sh[32][33];
    const int c0 = blockIdx.x * 32, r0 = blockIdx.y * 32;
    const int tx = threadIdx.x, ty = threadIdx.y;
#pragma unroll
    for (int k = 0; k < 4; k++) {
        int r = ty + k * 8;
        sh[r][tx] = q[(size_t)(r0 + r) * (3 * EDIM) + 2 * EDIM + c0 + tx];
    }
    __syncthreads();
#pragma unroll
    for (int k = 0; k < 4; k++) {
        int cc = ty + k * 8;
        t[(size_t)(c0 + cc) * NTOK + r0 + tx] = sh[tx][cc];
    }
}

// fp32 -> fp16 convert (vectorized by 4)
__global__ void conv_f16(const float* __restrict__ src,
                         __half* __restrict__ dst, int n4)
{
    int idx = blockIdx.x * blockDim.x + threadIdx.x;
    if (idx >= n4) return;
    float4 v = ((const float4*)src)[idx];
    uint2 ph;
    ph.x = pack2h(v.x, v.y); ph.y = pack2h(v.z, v.w);
    ((uint2*)dst)[idx] = ph;
}

// ---------------------------------------------------------------------------
extern "C" void kernel_launch(void* const* d_in, const int* in_sizes, int n_in,
                              void* d_out, int out_size)
{
    const float* mentions = (const float*)d_in[0];  // [2048,1024]
    const float* Wqkv     = (const float*)d_in[1];  // [4,3072,1024]
    const float* bqkv     = (const float*)d_in[2];  // [4,3072]
    const float* Wo       = (const float*)d_in[3];  // [4,1024,1024]
    const float* bo       = (const float*)d_in[4];  // [4,1024]
    float* out            = (float*)d_out;          // [2048,2048]

    __half *x, *qkv, *wh, *vT, *wv, *Wq, *Wl;
    float *p0, *p1;
    cudaGetSymbolAddress((void**)&x, g_x);
    cudaGetSymbolAddress((void**)&qkv, g_qkv);
    cudaGetSymbolAddress((void**)&p0, g_p0);  cudaGetSymbolAddress((void**)&p1, g_p1);
    cudaGetSymbolAddress((void**)&wh, g_wh);
    cudaGetSymbolAddress((void**)&vT, g_vT);
    cudaGetSymbolAddress((void**)&wv, g_wv);
    cudaGetSymbolAddress((void**)&Wq, g_Wqkv);
    cudaGetSymbolAddress((void**)&Wl, g_Wo);

    cudaFuncSetAttribute(gemm_mma<false, false>,
                         cudaFuncAttributeMaxDynamicSharedMemorySize, SMEM_BYTES);
    cudaFuncSetAttribute(gemm_mma<true, false>,
                         cudaFuncAttributeMaxDynamicSharedMemorySize, SMEM_BYTES);
    cudaFuncSetAttribute(gemm_mma<false, true>,
                         cudaFuncAttributeMaxDynamicSharedMemorySize, SMEM_BYTES);

    const float scale = 1.0f / 32.0f;   // 1/sqrt(1024)

    // Convert weights + input activations to fp16
    {
        int n4 = NLAYER * 3 * EDIM * EDIM / 4;
        conv_f16<<<(n4 + 255) / 256, 256>>>(Wqkv, Wq, n4);
        n4 = NLAYER * EDIM * EDIM / 4;
        conv_f16<<<(n4 + 255) / 256, 256>>>(Wo, Wl, n4);
        n4 = NTOK * EDIM / 4;
        conv_f16<<<(n4 + 255) / 256, 256>>>(mentions, x, n4);
    }

    for (int l = 0; l < NLAYER; l++) {
        const __half* Wqh = Wq + (size_t)l * 3 * EDIM * EDIM;
        const __half* Woh = Wl + (size_t)l * EDIM * EDIM;
        const float* bq = bqkv + (size_t)l * 3 * EDIM;
        const float* bl = bo   + (size_t)l * EDIM;

        // qkv partials = x @ Wqkv^T   (split-K x2)  [2048,3072] fp32
        gemm_mma<false, false><<<dim3(24, 16, 2), 256, SMEM_BYTES>>>(
            x, EDIM, Wqh, EDIM, p0, p1, 3 * EDIM, EDIM, 1.0f);
        // qkv = p0 + p1 + bqkv -> fp16
        combine_split<<<(NTOK * 3 * EDIM / 4 + 255) / 256, 256>>>(
            p0, p1, bq, qkv, 3 * EDIM, NTOK * 3 * EDIM / 4);

        // scores partials = scale * q @ k^T  (split-K x2, lower blocks only)
        gemm_mma<true, false><<<dim3(16, 16, 2), 256, SMEM_BYTES>>>(
            qkv, 3 * EDIM, qkv + EDIM, 3 * EDIM, p0, p1, NTOK, EDIM, scale);

        // softmax (sums partials) -> w fp16, accumulate 0.25*w into out
        softmax_causal_acc<<<NTOK, 256>>>(p0, p1, wh, out, l == 0 ? 1 : 0);

        // vT = transpose of v slice
        transpose_v<<<dim3(EDIM / 32, NTOK / 32), dim3(32, 8)>>>(qkv, vT);

        // wv partials = w @ v  (split-K x2, K limited per row-block)
        gemm_mma<false, true><<<dim3(8, 16, 2), 256, SMEM_BYTES>>>(
            wh, NTOK, vT, NTOK, p0, p1, EDIM, NTOK, 1.0f);
        combine_split<<<(NTOK * EDIM / 4 + 255) / 256, 256>>>(
            p0, p1, nullptr, wv, EDIM, NTOK * EDIM / 4);

        // x partials = wv @ Wo^T  (split-K x2)
        gemm_mma<false, false><<<dim3(8, 16, 2), 256, SMEM_BYTES>>>(
            wv, EDIM, Woh, EDIM, p0, p1, EDIM, EDIM, 1.0f);
        combine_split<<<(NTOK * EDIM / 4 + 255) / 256, 256>>>(
            p0, p1, bl, x, EDIM, NTOK * EDIM / 4);
    }
}